// round 14
// baseline (speedup 1.0000x reference)
#include <cuda_runtime.h>
#include <cuda_bf16.h>

// WaveletParsingLayer: x3 [B=128, N_SEG=128, SEG_LEN=2048] f32, tail half
// (k >= 1024) of each segment is the filler 10.1f. Output [B, N_SEG*1024]
// == strided copy of the first 1024 f32 of each 2048-f32 segment.
//
// float4 units: o4 = (b*128+s)*256 + k4 ; src4 = ((o4>>8)<<9) | (o4&255)
// total out f4 = 4,194,304 = 1024 blocks * 256 threads * 16
//
// R13 change vs R12: __stcs -> __stwt. Evidence: timed dur == ncu
// cold-cache dur (18.94 vs 18.91) => zero replay L2 reuse, because the
// 67 MB read set + 67 MB of store-line allocations = 134 MB > 126 MB L2
// and the read set thrashes every replay. st.global.wt writes through
// without holding L2 capacity, so the 67 MB read set alone fits and
// stays resident across graph replays: warm replays read from L2 and
// DRAM carries only the write stream (~9 us DRAM floor, ~12 us LTS floor).
// Launch config unchanged from measured best: single wave, 1024 CTAs,
// 16 f4/thread in two 8-deep batched passes, regs pinned to 32.

__global__ __launch_bounds__(256, 8) void wavelet_compact_copy(
    const float4* __restrict__ src, float4* __restrict__ dst)
{
    unsigned cta_base = blockIdx.x * 4096u + threadIdx.x;

#pragma unroll
    for (int half = 0; half < 2; ++half) {
        unsigned base = cta_base + (unsigned)half * 2048u;
        float4 v[8];
#pragma unroll
        for (int i = 0; i < 8; ++i) {
            unsigned o4 = base + (unsigned)i * 256u;
            unsigned s4 = ((o4 >> 8) << 9) | (o4 & 255u);
            v[i] = __ldg(&src[s4]);
        }
#pragma unroll
        for (int i = 0; i < 8; ++i) {
            unsigned o4 = base + (unsigned)i * 256u;
            __stwt(&dst[o4], v[i]);
        }
    }
}

extern "C" void kernel_launch(void* const* d_in, const int* in_sizes, int n_in,
                              void* d_out, int out_size)
{
    // metadata order: x1 [128,64] f32 (unused), x2 [128,64] f32 (unused),
    //                 x3 [128,128,2048] f32
    const float4* x3 = (const float4*)d_in[2];
    float4* out = (float4*)d_out;

    wavelet_compact_copy<<<1024, 256>>>(x3, out);
}